// round 3
// baseline (speedup 1.0000x reference)
#include <cuda_runtime.h>
#include <math.h>

#define T_STEPS 400
#define BATCH   128
#define HID     512
#define OC      64
#define NCH1    9
#define NCH2    16

typedef unsigned long long ull;

// ---------------- device scratch ----------------
__device__ float g_ybuf[OC * T_STEPS * BATCH];   // [oc][t][b]
__device__ float g_seq [T_STEPS * OC * BATCH];   // [t][c][b]
__device__ float g_scale[OC];
__device__ float g_shift[OC];
__device__ float g_memL[2][OC * BATCH];
__device__ float g_mem1[2][HID * BATCH];
__device__ float g_syn1[HID * BATCH];
__device__ float g_spk1[HID * BATCH];
__device__ float g_mem2[2][HID * BATCH];
__device__ float g_syn2[HID * BATCH];
__device__ float g_acc2[HID * BATCH];
// packed duplicated weights: [cta][ch][16 rows][64 k] as (w,w) u64 pairs
__device__ ull   g_wp1[128 * NCH1 * 16 * 64];
__device__ ull   g_wp2[128 * NCH2 * 16 * 64];
__device__ float g_bias1[4 * HID];
__device__ float g_bias2[4 * HID];

// ---------------- helpers ----------------
__device__ __forceinline__ float sigf(float x) { return 1.f / (1.f + expf(-x)); }

__device__ __forceinline__ ull packf2(float w) {
    ull r; unsigned u = __float_as_uint(w);
    asm("mov.b64 %0, {%1, %1};" : "=l"(r) : "r"(u));
    return r;
}
__device__ __forceinline__ void fma2(ull& acc, ull a, ull b) {
    asm("fma.rn.f32x2 %0, %1, %2, %0;" : "+l"(acc) : "l"(a), "l"(b));
}
__device__ __forceinline__ void unpack2(ull a, float& lo, float& hi) {
    unsigned l, h; asm("mov.b64 {%0,%1},%2;" : "=r"(l), "=r"(h) : "l"(a));
    lo = __uint_as_float(l); hi = __uint_as_float(h);
}
__device__ __forceinline__ void cpa16(void* dst_smem, const void* src) {
    unsigned d = (unsigned)__cvta_generic_to_shared(dst_smem);
    asm volatile("cp.async.ca.shared.global [%0], [%1], 16;" :: "r"(d), "l"(src));
}
#define CP_COMMIT() asm volatile("cp.async.commit_group;" ::: "memory")
#define CP_WAIT1()  asm volatile("cp.async.wait_group 1;"  ::: "memory")

// ---------------- init ----------------
__global__ void init_kernel() {
    int i = blockIdx.x * 256 + threadIdx.x;          // grid covers 131072
    if (i < 2 * OC * BATCH) ((float*)g_memL)[i] = 0.f;
    if (i < 2 * HID * BATCH) { ((float*)g_mem1)[i] = 0.f; ((float*)g_mem2)[i] = 0.f; }
    if (i < HID * BATCH) { g_syn1[i] = 0.f; g_spk1[i] = 0.f; g_syn2[i] = 0.f; g_acc2[i] = 0.f; }
}

// ---------------- weight packing ----------------
// layer1: K layout = 64 (ih) + 512 (hh), 9 chunks of 64
__global__ void pack1_kernel(const float* __restrict__ w_ih, const float* __restrict__ w_hh,
                             const float* __restrict__ bi, const float* __restrict__ bh) {
    int i = blockIdx.x * 256 + threadIdx.x;
    if (i < 4 * HID) g_bias1[i] = bi[i] + bh[i];
    if (i >= 128 * NCH1 * 16 * 64) return;
    int kk = i & 63; int tmp = i >> 6; int r = tmp & 15; int tmp2 = tmp >> 4;
    int ch = tmp2 % NCH1; int cta = tmp2 / NCH1;
    int grow = (r >> 2) * HID + cta * 4 + (r & 3);
    int k = ch * 64 + kk;
    float w = (k < 64) ? w_ih[grow * 64 + k] : w_hh[grow * HID + (k - 64)];
    g_wp1[i] = packf2(w);
}
// layer2: K layout = 512 (ih, input=spk1) + 512 (hh), 16 chunks
__global__ void pack2_kernel(const float* __restrict__ w_ih, const float* __restrict__ w_hh,
                             const float* __restrict__ bi, const float* __restrict__ bh) {
    int i = blockIdx.x * 256 + threadIdx.x;
    if (i < 4 * HID) g_bias2[i] = bi[i] + bh[i];
    if (i >= 128 * NCH2 * 16 * 64) return;
    int kk = i & 63; int tmp = i >> 6; int r = tmp & 15; int tmp2 = tmp >> 4;
    int ch = tmp2 & 15; int cta = tmp2 >> 4;
    int grow = (r >> 2) * HID + cta * 4 + (r & 3);
    int k = ch * 64 + kk;
    float w = (k < HID) ? w_ih[grow * HID + k] : w_hh[grow * HID + (k - HID)];
    g_wp2[i] = packf2(w);
}

// ---------------- conv1d (pad=2, k=5): block=t, threads=b ----------------
__global__ void conv_kernel(const float* __restrict__ x, const float* __restrict__ w) {
    __shared__ float s_w[OC * 70];
    int t = blockIdx.x, b = threadIdx.x;
    for (int i = b; i < OC * 70; i += 128) s_w[i] = w[i];
    float xr[5][14];
#pragma unroll
    for (int k = 0; k < 5; k++) {
        int tt = t + k - 2;
        bool ok = (tt >= 0 && tt < T_STEPS);
#pragma unroll
        for (int c = 0; c < 14; c++)
            xr[k][c] = ok ? x[(tt * BATCH + b) * 14 + c] : 0.f;
    }
    __syncthreads();
    for (int oc = 0; oc < OC; oc++) {
        float acc = 0.f;
        const float* wr = s_w + oc * 70;
#pragma unroll
        for (int c = 0; c < 14; c++)
#pragma unroll
            for (int k = 0; k < 5; k++)
                acc = fmaf(xr[k][c], wr[c * 5 + k], acc);
        g_ybuf[oc * (T_STEPS * BATCH) + t * BATCH + b] = acc;
    }
}

__global__ void stats_kernel(const float* __restrict__ bn_g, const float* __restrict__ bn_b) {
    int c = blockIdx.x;
    const float* base = g_ybuf + c * (T_STEPS * BATCH);
    double s = 0.0, sq = 0.0;
    for (int i = threadIdx.x; i < T_STEPS * BATCH; i += 256) {
        float v = base[i];
        s += v; sq += (double)v * (double)v;
    }
    __shared__ double rs[256], rq[256];
    rs[threadIdx.x] = s; rq[threadIdx.x] = sq;
    __syncthreads();
    for (int st = 128; st > 0; st >>= 1) {
        if (threadIdx.x < st) { rs[threadIdx.x] += rs[threadIdx.x + st]; rq[threadIdx.x] += rq[threadIdx.x + st]; }
        __syncthreads();
    }
    if (threadIdx.x == 0) {
        double n = (double)(T_STEPS * BATCH);
        double mu = rs[0] / n;
        double var = rq[0] / n - mu * mu;
        float sc = bn_g[c] * (float)(1.0 / sqrt(var + 1e-5));
        g_scale[c] = sc;
        g_shift[c] = bn_b[c] - (float)mu * sc;
    }
}

__global__ void norm_kernel() {
    int i = blockIdx.x * 256 + threadIdx.x;
    if (i >= OC * T_STEPS * BATCH) return;
    int oc = i / (T_STEPS * BATCH);
    int rem = i % (T_STEPS * BATCH);
    int t = rem / BATCH, b = rem % BATCH;
    g_seq[t * (OC * BATCH) + oc * BATCH + b] = g_ybuf[i] * g_scale[oc] + g_shift[oc];
}

// ---------------- step kernels ----------------
// smem: state 2 x 64x128 f32 (64KB) + weights 2 x 16 rows x 68 ull (17KB)
#define SMEM_STEP (2 * 64 * 128 * 4 + 2 * 16 * 68 * 8)

__device__ __forceinline__ void gemm_chunk(const float* __restrict__ st,
                                           const ull* __restrict__ w,
                                           int hh, int bc, ull acc[4]) {
    const ull* w0 = w + (0  + hh) * 68;
    const ull* w1 = w + (4  + hh) * 68;
    const ull* w2 = w + (8  + hh) * 68;
    const ull* w3 = w + (12 + hh) * 68;
    const float* sp = st + bc * 2;
#pragma unroll 8
    for (int kk = 0; kk < 64; kk += 2) {
        ull s0 = *(const ull*)(sp + kk * 128);
        ull s1 = *(const ull*)(sp + kk * 128 + 128);
        ulonglong2 a0 = *(const ulonglong2*)(w0 + kk);
        ulonglong2 a1 = *(const ulonglong2*)(w1 + kk);
        ulonglong2 a2 = *(const ulonglong2*)(w2 + kk);
        ulonglong2 a3 = *(const ulonglong2*)(w3 + kk);
        fma2(acc[0], s0, a0.x); fma2(acc[0], s1, a0.y);
        fma2(acc[1], s0, a1.x); fma2(acc[1], s1, a1.y);
        fma2(acc[2], s0, a2.x); fma2(acc[2], s1, a2.y);
        fma2(acc[3], s0, a3.x); fma2(acc[3], s1, a3.y);
    }
}

template <int MODE, int NCH>
__global__ void __launch_bounds__(256) step_kernel(int t,
    const float* __restrict__ thrA_p, const float* __restrict__ thr_p)
{
    extern __shared__ char smem[];
    float* s_state = (float*)smem;                 // 2 * 8192
    ull*   s_w     = (ull*)(smem + 65536);         // 2 * 16*68
    const int tid = threadIdx.x;
    const int hh = tid & 3, bc = tid >> 2;
    const int h0 = blockIdx.x * 4;
    const int cur = t & 1, nxt = cur ^ 1;
    const float thr = *thr_p;

    auto fetch_state = [&](int ch, int buf) {
        const float* src;
        if (MODE == 1) src = g_mem1[cur] + (ch - 1) * 8192;
        else src = (ch < 8) ? g_spk1 + ch * 8192 : g_mem2[cur] + (ch - 8) * 8192;
        float* dst = s_state + buf * 8192;
#pragma unroll
        for (int j = 0; j < 8; j++) {
            int u = tid + j * 256;
            cpa16(dst + u * 4, src + u * 4);
        }
    };
    auto fetch_w = [&](int ch, int buf) {
        const ull* src = (MODE == 1 ? g_wp1 : g_wp2) + (size_t)(blockIdx.x * NCH + ch) * 1024;
        ull* dst = s_w + buf * (16 * 68);
#pragma unroll
        for (int j = 0; j < 2; j++) {
            int u = tid + j * 256;
            int row = u >> 5, col = u & 31;
            cpa16(dst + row * 68 + col * 2, src + u * 2);
        }
    };

    if (MODE == 1) {
        fetch_w(0, 0); CP_COMMIT();                       // group 0
        fetch_state(1, 1); fetch_w(1, 1); CP_COMMIT();    // group 1
        const float thrL = *thrA_p;
        for (int i = tid; i < 8192; i += 256) {           // LIF spikes -> buf 0
            float old = g_memL[cur][i];
            float xt = g_seq[t * 8192 + i];
            float reset = (old > thrL) ? thrL : 0.f;
            float mn = 0.9f * old + xt - reset;
            if (blockIdx.x == 0) g_memL[nxt][i] = mn;
            s_state[i] = (mn > thrL) ? 1.f : 0.f;
        }
    } else {
        fetch_state(0, 0); fetch_w(0, 0); CP_COMMIT();
        fetch_state(1, 1); fetch_w(1, 1); CP_COMMIT();
    }

    ull acc[4] = {0ull, 0ull, 0ull, 0ull};
    for (int ch = 0; ch < NCH; ch++) {
        int buf = ch & 1;
        CP_WAIT1();
        __syncthreads();
        gemm_chunk(s_state + buf * 8192, s_w + buf * (16 * 68), hh, bc, acc);
        __syncthreads();
        if (ch + 2 < NCH) { fetch_state(ch + 2, buf); fetch_w(ch + 2, buf); }
        CP_COMMIT();
    }

    // epilogue: thread owns hidden h0+hh, batch {bc*2, bc*2+1}; acc = i,f,g,o
    const float* bias = (MODE == 1) ? g_bias1 : g_bias2;
    float bi_ = bias[0 * HID + h0 + hh];
    float bf_ = bias[1 * HID + h0 + hh];
    float bg_ = bias[2 * HID + h0 + hh];
    float bo_ = bias[3 * HID + h0 + hh];
    float xi[2], xf[2], xg[2], xo[2];
    unpack2(acc[0], xi[0], xi[1]);
    unpack2(acc[1], xf[0], xf[1]);
    unpack2(acc[2], xg[0], xg[1]);
    unpack2(acc[3], xo[0], xo[1]);
    int idx = (h0 + hh) * 128 + bc * 2;
#pragma unroll
    for (int e = 0; e < 2; e++) {
        float iv = xi[e] + bi_, fv = xf[e] + bf_, gv = xg[e] + bg_, ov = xo[e] + bo_;
        float syn, memo;
        if (MODE == 1) { syn = g_syn1[idx + e]; memo = g_mem1[cur][idx + e]; }
        else           { syn = g_syn2[idx + e]; memo = g_mem2[cur][idx + e]; }
        float reset = (memo > thr) ? thr : 0.f;
        float sn = sigf(fv) * syn + sigf(iv) * tanhf(gv);
        float mn = sigf(ov) * tanhf(sn) - reset;
        if (MODE == 1) {
            g_syn1[idx + e] = sn;
            g_mem1[nxt][idx + e] = mn;
            g_spk1[idx + e] = (mn > thr) ? 1.f : 0.f;
        } else {
            g_syn2[idx + e] = sn;
            g_mem2[nxt][idx + e] = mn;
            g_acc2[idx + e] += mn;
        }
    }
}

// ---------------- heads ----------------
__global__ void heads_kernel(const float* __restrict__ wg, const float* __restrict__ bg,
                             const float* __restrict__ wd1, const float* __restrict__ bd1,
                             const float* __restrict__ wd2, const float* __restrict__ bd2,
                             const float* __restrict__ thr_dom_p, float* __restrict__ out)
{
    __shared__ float feat[512];
    __shared__ float sd[64];
    int b = blockIdx.x, tid = threadIdx.x;
    const float thr = *thr_dom_p;
#pragma unroll
    for (int j = 0; j < 4; j++)
        feat[tid + j * 128] = g_acc2[(tid + j * 128) * 128 + b] * (1.f / 400.f);
    __syncthreads();
    if (tid < 8) {
        float acc = bg[tid];
        for (int h = 0; h < 512; h++) acc = fmaf(feat[h], wg[tid * 512 + h], acc);
        out[b * 8 + tid] = acc;
    }
    if (tid < 64) {
        float acc = bd1[tid];
        for (int h = 0; h < 512; h++) acc = fmaf(feat[h], wd1[tid * 512 + h], acc);
        sd[tid] = (acc - thr > 0.f) ? 1.f : 0.f;
    }
    __syncthreads();
    if (tid < 10) {
        float acc = bd2[tid];
        for (int k = 0; k < 64; k++) acc = fmaf(sd[k], wd2[tid * 64 + k], acc);
        out[128 * 8 + b * 10 + tid] = acc;
    }
}

extern "C" void kernel_launch(void* const* d_in, const int* in_sizes, int n_in,
                              void* d_out, int out_size) {
    const float* x       = (const float*)d_in[0];
    const float* conv_w  = (const float*)d_in[1];
    const float* bn_g    = (const float*)d_in[2];
    const float* bn_b    = (const float*)d_in[3];
    const float* w_ih1   = (const float*)d_in[4];
    const float* w_hh1   = (const float*)d_in[5];
    const float* b_ih1   = (const float*)d_in[6];
    const float* b_hh1   = (const float*)d_in[7];
    const float* w_ih2   = (const float*)d_in[8];
    const float* w_hh2   = (const float*)d_in[9];
    const float* b_ih2   = (const float*)d_in[10];
    const float* b_hh2   = (const float*)d_in[11];
    const float* wg      = (const float*)d_in[12];
    const float* bg      = (const float*)d_in[13];
    const float* wd1     = (const float*)d_in[14];
    const float* bd1     = (const float*)d_in[15];
    const float* wd2     = (const float*)d_in[16];
    const float* bd2     = (const float*)d_in[17];
    const float* thrL    = (const float*)d_in[18];
    const float* thr1    = (const float*)d_in[19];
    const float* thr2    = (const float*)d_in[20];
    const float* thrD    = (const float*)d_in[21];

    cudaFuncSetAttribute(step_kernel<1, NCH1>, cudaFuncAttributeMaxDynamicSharedMemorySize, SMEM_STEP);
    cudaFuncSetAttribute(step_kernel<2, NCH2>, cudaFuncAttributeMaxDynamicSharedMemorySize, SMEM_STEP);

    init_kernel<<<512, 256>>>();
    pack1_kernel<<<(128 * NCH1 * 16 * 64 + 255) / 256, 256>>>(w_ih1, w_hh1, b_ih1, b_hh1);
    pack2_kernel<<<(128 * NCH2 * 16 * 64 + 255) / 256, 256>>>(w_ih2, w_hh2, b_ih2, b_hh2);
    conv_kernel<<<T_STEPS, 128>>>(x, conv_w);
    stats_kernel<<<OC, 256>>>(bn_g, bn_b);
    norm_kernel<<<(OC * T_STEPS * BATCH + 255) / 256, 256>>>();
    for (int t = 0; t < T_STEPS; t++) {
        step_kernel<1, NCH1><<<128, 256, SMEM_STEP>>>(t, thrL, thr1);
        step_kernel<2, NCH2><<<128, 256, SMEM_STEP>>>(t, thr2, thr2);
    }
    heads_kernel<<<128, 128>>>(wg, bg, wd1, bd1, wd2, bd2, thrD, (float*)d_out);
}

// round 4
// speedup vs baseline: 1.6002x; 1.6002x over previous
#include <cuda_runtime.h>
#include <math.h>

#define T_STEPS 400
#define BATCH   128
#define HID     512
#define OC      64

typedef unsigned long long ull;

// ---------------- device scratch ----------------
__device__ float g_ybuf[OC * T_STEPS * BATCH];   // [oc][t][b]
__device__ float g_seq [T_STEPS * OC * BATCH];   // [t][c][b]
__device__ float g_scale[OC];
__device__ float g_shift[OC];
__device__ float g_memL[OC * BATCH];
__device__ float g_S1[576 * BATCH];              // rows 0-63 spikes, 64-575 mem1
__device__ float g_S2[1024 * BATCH];             // rows 0-511 spk1, 512-1023 mem2
__device__ float g_syn1[HID * BATCH];
__device__ float g_syn2[HID * BATCH];
__device__ float g_acc2[HID * BATCH];
__device__ float g_part[8 * 2048 * BATCH];       // split-K partials (reused A/B)
__device__ float g_wpk1[128 * 72 * 128];         // [cta][klocal][gate128]
__device__ float g_wpk2[128 * 128 * 128];
__device__ float g_bias1[2048];
__device__ float g_bias2[2048];
__device__ unsigned g_bar_count;
__device__ volatile unsigned g_bar_phase;

// ---------------- helpers ----------------
__device__ __forceinline__ float sigf(float x) { return 1.f / (1.f + expf(-x)); }
__device__ __forceinline__ ull packf2(float w) {
    ull r; unsigned u = __float_as_uint(w);
    asm("mov.b64 %0, {%1, %1};" : "=l"(r) : "r"(u));
    return r;
}
__device__ __forceinline__ void fma2(ull& acc, ull a, ull b) {
    asm("fma.rn.f32x2 %0, %1, %2, %0;" : "+l"(acc) : "l"(a), "l"(b));
}
__device__ __forceinline__ void cpa16cg(void* dst_smem, const void* src) {
    unsigned d = (unsigned)__cvta_generic_to_shared(dst_smem);
    asm volatile("cp.async.cg.shared.global [%0], [%1], 16;" :: "r"(d), "l"(src));
}
#define CP_COMMIT() asm volatile("cp.async.commit_group;" ::: "memory")
#define CP_WAIT1()  asm volatile("cp.async.wait_group 1;"  ::: "memory")
#define CP_WAIT0()  asm volatile("cp.async.wait_group 0;"  ::: "memory")

__device__ __forceinline__ void grid_barrier() {
    __syncthreads();
    if (threadIdx.x == 0) {
        unsigned ph = g_bar_phase;
        __threadfence();
        if (atomicAdd(&g_bar_count, 1) == gridDim.x - 1) {
            g_bar_count = 0;
            __threadfence();
            g_bar_phase = ph + 1;
        } else {
            while (g_bar_phase == ph) __nanosleep(64);
        }
    }
    __syncthreads();
}

// ---------------- init ----------------
__global__ void init_kernel() {
    int i = blockIdx.x * 256 + threadIdx.x;      // grid covers 409600
    if (i == 0) { g_bar_count = 0; g_bar_phase = 0; }
    if (i < 576 * BATCH) g_S1[i] = 0.f;
    if (i < 1024 * BATCH) g_S2[i] = 0.f;
    if (i < HID * BATCH) { g_syn1[i] = 0.f; g_syn2[i] = 0.f; g_acc2[i] = 0.f; }
    if (i < OC * BATCH) g_memL[i] = 0.f;
}

// ---------------- weight packing ----------------
__global__ void pack1_kernel(const float* __restrict__ w_ih, const float* __restrict__ w_hh,
                             const float* __restrict__ bi, const float* __restrict__ bh) {
    int i = blockIdx.x * 256 + threadIdx.x;
    if (i < 2048) g_bias1[i] = bi[i] + bh[i];
    if (i >= 128 * 72 * 128) return;
    int gi = i & 127; int rem = i >> 7;
    int kl = rem % 72; int cta = rem / 72;
    int tile = cta >> 3, split = cta & 7;
    int r = tile * 128 + gi;
    int kg = split * 72 + kl;
    g_wpk1[i] = (kg < 64) ? w_ih[r * 64 + kg] : w_hh[r * 512 + kg - 64];
}
__global__ void pack2_kernel(const float* __restrict__ w_ih, const float* __restrict__ w_hh,
                             const float* __restrict__ bi, const float* __restrict__ bh) {
    int i = blockIdx.x * 256 + threadIdx.x;
    if (i < 2048) g_bias2[i] = bi[i] + bh[i];
    if (i >= 128 * 128 * 128) return;
    int gi = i & 127; int rem = i >> 7;
    int kl = rem & 127; int cta = rem >> 7;
    int tile = cta >> 3, split = cta & 7;
    int r = tile * 128 + gi;
    int kg = split * 128 + kl;
    g_wpk2[i] = (kg < 512) ? w_ih[r * 512 + kg] : w_hh[r * 512 + kg - 512];
}

// ---------------- conv1d (pad=2, k=5): block=t, threads=b ----------------
__global__ void conv_kernel(const float* __restrict__ x, const float* __restrict__ w) {
    __shared__ float s_w[OC * 70];
    int t = blockIdx.x, b = threadIdx.x;
    for (int i = b; i < OC * 70; i += 128) s_w[i] = w[i];
    float xr[5][14];
#pragma unroll
    for (int k = 0; k < 5; k++) {
        int tt = t + k - 2;
        bool ok = (tt >= 0 && tt < T_STEPS);
#pragma unroll
        for (int c = 0; c < 14; c++)
            xr[k][c] = ok ? x[(tt * BATCH + b) * 14 + c] : 0.f;
    }
    __syncthreads();
    for (int oc = 0; oc < OC; oc++) {
        float acc = 0.f;
        const float* wr = s_w + oc * 70;
#pragma unroll
        for (int c = 0; c < 14; c++)
#pragma unroll
            for (int k = 0; k < 5; k++)
                acc = fmaf(xr[k][c], wr[c * 5 + k], acc);
        g_ybuf[oc * (T_STEPS * BATCH) + t * BATCH + b] = acc;
    }
}

__global__ void stats_kernel(const float* __restrict__ bn_g, const float* __restrict__ bn_b) {
    int c = blockIdx.x;
    const float* base = g_ybuf + c * (T_STEPS * BATCH);
    double s = 0.0, sq = 0.0;
    for (int i = threadIdx.x; i < T_STEPS * BATCH; i += 256) {
        float v = base[i];
        s += v; sq += (double)v * (double)v;
    }
    __shared__ double rs[256], rq[256];
    rs[threadIdx.x] = s; rq[threadIdx.x] = sq;
    __syncthreads();
    for (int st = 128; st > 0; st >>= 1) {
        if (threadIdx.x < st) { rs[threadIdx.x] += rs[threadIdx.x + st]; rq[threadIdx.x] += rq[threadIdx.x + st]; }
        __syncthreads();
    }
    if (threadIdx.x == 0) {
        double n = (double)(T_STEPS * BATCH);
        double mu = rs[0] / n;
        double var = rq[0] / n - mu * mu;
        float sc = bn_g[c] * (float)(1.0 / sqrt(var + 1e-5));
        g_scale[c] = sc;
        g_shift[c] = bn_b[c] - (float)mu * sc;
    }
}

__global__ void norm_kernel() {
    int i = blockIdx.x * 256 + threadIdx.x;
    if (i >= OC * T_STEPS * BATCH) return;
    int oc = i / (T_STEPS * BATCH);
    int rem = i % (T_STEPS * BATCH);
    int t = rem / BATCH, b = rem % BATCH;
    g_seq[t * (OC * BATCH) + oc * BATCH + b] = g_ybuf[i] * g_scale[oc] + g_shift[oc];
}

// ---------------- persistent scan kernel ----------------
// grid 128 = 16 gate-tiles x 8 k-splits; 128 threads; thread tile 8 gates x 16 batch
// smem: w1 [72][128] + w2 [128][128] + state dbuf [2][24*128]

template <int KS, int CH>
__device__ __forceinline__ void gemm_phase(const float* __restrict__ gstate,
                                           const float* __restrict__ wsm,
                                           float* __restrict__ spart,
                                           float* __restrict__ sbuf,
                                           int gg, int bgr)
{
    const int NCHK = KS / CH;
    const int tid = threadIdx.x;

    // prologue: fetch chunks 0 and 1
#pragma unroll
    for (int j = 0; j < CH / 4; j++) {
        int u = tid + j * 128;
        cpa16cg(sbuf + u * 4, gstate + u * 4);
    }
    CP_COMMIT();
    if (NCHK > 1) {
#pragma unroll
        for (int j = 0; j < CH / 4; j++) {
            int u = tid + j * 128;
            cpa16cg(sbuf + CH * 128 + u * 4, gstate + CH * 128 + u * 4);
        }
    }
    CP_COMMIT();

    ull acc[8][8];
#pragma unroll
    for (int j = 0; j < 8; j++)
#pragma unroll
        for (int q = 0; q < 8; q++) acc[j][q] = 0ull;

    for (int c = 0; c < NCHK; c++) {
        CP_WAIT1();
        __syncthreads();
        const float* sb = sbuf + (c & 1) * (CH * 128) + bgr * 16;
        const float* wb = wsm + c * (CH * 128) + gg * 8;
#pragma unroll 2
        for (int kk = 0; kk < CH; kk++) {
            ulonglong2 sA = *(const ulonglong2*)(sb + kk * 128);
            ulonglong2 sB = *(const ulonglong2*)(sb + kk * 128 + 4);
            ulonglong2 sC = *(const ulonglong2*)(sb + kk * 128 + 8);
            ulonglong2 sD = *(const ulonglong2*)(sb + kk * 128 + 12);
            float4 w03 = *(const float4*)(wb + kk * 128);
            float4 w47 = *(const float4*)(wb + kk * 128 + 4);
            float wv[8] = {w03.x, w03.y, w03.z, w03.w, w47.x, w47.y, w47.z, w47.w};
            ull s[8] = {sA.x, sA.y, sB.x, sB.y, sC.x, sC.y, sD.x, sD.y};
#pragma unroll
            for (int j = 0; j < 8; j++) {
                ull wp = packf2(wv[j]);
#pragma unroll
                for (int q = 0; q < 8; q++) fma2(acc[j][q], s[q], wp);
            }
        }
        __syncthreads();
        if (c + 2 < NCHK) {
            const float* src = gstate + (c + 2) * (CH * 128);
            float* dst = sbuf + (c & 1) * (CH * 128);
#pragma unroll
            for (int j = 0; j < CH / 4; j++) {
                int u = tid + j * 128;
                cpa16cg(dst + u * 4, src + u * 4);
            }
        }
        CP_COMMIT();
    }

    // write partials: rows gg*8+j, cols bgr*16..+16
#pragma unroll
    for (int j = 0; j < 8; j++) {
        float* dst = spart + (gg * 8 + j) * 128 + bgr * 16;
#pragma unroll
        for (int q = 0; q < 4; q++) {
            ulonglong2 v; v.x = acc[j][2 * q]; v.y = acc[j][2 * q + 1];
            *(ulonglong2*)(dst + q * 4) = v;
        }
    }
}

__device__ __forceinline__ void epi_slstm(int layer, float thr) {
    const float* bias = (layer == 1) ? g_bias1 : g_bias2;
    float* syn  = (layer == 1) ? g_syn1 : g_syn2;
    float* memr = (layer == 1) ? (g_S1 + 64 * 128) : (g_S2 + 512 * 128);
    int tg = blockIdx.x * 128 + threadIdx.x;
#pragma unroll
    for (int e4 = 0; e4 < 4; e4++) {
        int e = tg + e4 * 16384;
        int h = e >> 7, b = e & 127;
        float sums[4];
#pragma unroll
        for (int gt = 0; gt < 4; gt++) {
            int r = gt * 512 + h;
            float s = 0.f;
#pragma unroll
            for (int sp = 0; sp < 8; sp++)
                s += __ldcg(&g_part[sp * 262144 + r * 128 + b]);
            sums[gt] = s + bias[r];
        }
        float sv = syn[e];
        float mo = __ldcg(&memr[e]);
        float reset = (mo > thr) ? thr : 0.f;
        float sn = sigf(sums[1]) * sv + sigf(sums[0]) * tanhf(sums[2]);
        float mn = sigf(sums[3]) * tanhf(sn) - reset;
        syn[e] = sn;
        memr[e] = mn;
        if (layer == 1) g_S2[e] = (mn > thr) ? 1.f : 0.f;
        else g_acc2[e] += mn;
    }
}

__device__ __forceinline__ void lif_phase(int t, float thrL) {
    int tg = blockIdx.x * 128 + threadIdx.x;
    if (tg < 8192) {
        float mo = g_memL[tg];
        float xt = g_seq[t * 8192 + tg];
        float reset = (mo > thrL) ? thrL : 0.f;
        float mn = 0.9f * mo + xt - reset;
        g_memL[tg] = mn;
        g_S1[tg] = (mn > thrL) ? 1.f : 0.f;
    }
}

__global__ void __launch_bounds__(128, 1) scan_kernel(
    const float* __restrict__ thrL_p, const float* __restrict__ thr1_p,
    const float* __restrict__ thr2_p)
{
    extern __shared__ float smem[];
    float* w1sm = smem;                 // 72*128  = 9216
    float* w2sm = smem + 9216;          // 128*128 = 16384
    float* sbuf = smem + 9216 + 16384;  // 2*24*128 = 6144

    const int tid = threadIdx.x;
    const int cta = blockIdx.x;
    const int tile = cta >> 3, split = cta & 7;
    const int gg = tid >> 3, bgr = tid & 7;
    const float thrL = __ldg(thrL_p), thr1 = __ldg(thr1_p), thr2 = __ldg(thr2_p);

    // load resident weights
    {
        const float* src1 = g_wpk1 + (size_t)cta * (72 * 128);
        for (int j = 0; j < 18; j++) {
            int u = tid + j * 128;
            cpa16cg(w1sm + u * 4, src1 + u * 4);
        }
        const float* src2 = g_wpk2 + (size_t)cta * (128 * 128);
        for (int j = 0; j < 32; j++) {
            int u = tid + j * 128;
            cpa16cg(w2sm + u * 4, src2 + u * 4);
        }
        CP_COMMIT(); CP_WAIT0();
        __syncthreads();
    }

    float* spart = g_part + split * 262144 + tile * 16384;

    lif_phase(0, thrL);
    grid_barrier();

    for (int t = 0; t < T_STEPS; t++) {
        gemm_phase<72, 24>(g_S1 + split * (72 * 128), w1sm, spart, sbuf, gg, bgr);
        grid_barrier();
        epi_slstm(1, thr1);
        grid_barrier();
        gemm_phase<128, 16>(g_S2 + split * (128 * 128), w2sm, spart, sbuf, gg, bgr);
        grid_barrier();
        epi_slstm(2, thr2);
        if (t + 1 < T_STEPS) lif_phase(t + 1, thrL);
        grid_barrier();
    }
}

// ---------------- heads ----------------
__global__ void heads_kernel(const float* __restrict__ wg, const float* __restrict__ bg,
                             const float* __restrict__ wd1, const float* __restrict__ bd1,
                             const float* __restrict__ wd2, const float* __restrict__ bd2,
                             const float* __restrict__ thr_dom_p, float* __restrict__ out)
{
    __shared__ float feat[512];
    __shared__ float sd[64];
    int b = blockIdx.x, tid = threadIdx.x;
    const float thr = *thr_dom_p;
#pragma unroll
    for (int j = 0; j < 4; j++)
        feat[tid + j * 128] = g_acc2[(tid + j * 128) * 128 + b] * (1.f / 400.f);
    __syncthreads();
    if (tid < 8) {
        float acc = bg[tid];
        for (int h = 0; h < 512; h++) acc = fmaf(feat[h], wg[tid * 512 + h], acc);
        out[b * 8 + tid] = acc;
    }
    if (tid < 64) {
        float acc = bd1[tid];
        for (int h = 0; h < 512; h++) acc = fmaf(feat[h], wd1[tid * 512 + h], acc);
        sd[tid] = (acc - thr > 0.f) ? 1.f : 0.f;
    }
    __syncthreads();
    if (tid < 10) {
        float acc = bd2[tid];
        for (int k = 0; k < 64; k++) acc = fmaf(sd[k], wd2[tid * 64 + k], acc);
        out[128 * 8 + b * 10 + tid] = acc;
    }
}

extern "C" void kernel_launch(void* const* d_in, const int* in_sizes, int n_in,
                              void* d_out, int out_size) {
    const float* x       = (const float*)d_in[0];
    const float* conv_w  = (const float*)d_in[1];
    const float* bn_g    = (const float*)d_in[2];
    const float* bn_b    = (const float*)d_in[3];
    const float* w_ih1   = (const float*)d_in[4];
    const float* w_hh1   = (const float*)d_in[5];
    const float* b_ih1   = (const float*)d_in[6];
    const float* b_hh1   = (const float*)d_in[7];
    const float* w_ih2   = (const float*)d_in[8];
    const float* w_hh2   = (const float*)d_in[9];
    const float* b_ih2   = (const float*)d_in[10];
    const float* b_hh2   = (const float*)d_in[11];
    const float* wg      = (const float*)d_in[12];
    const float* bg      = (const float*)d_in[13];
    const float* wd1     = (const float*)d_in[14];
    const float* bd1     = (const float*)d_in[15];
    const float* wd2     = (const float*)d_in[16];
    const float* bd2     = (const float*)d_in[17];
    const float* thrL    = (const float*)d_in[18];
    const float* thr1    = (const float*)d_in[19];
    const float* thr2    = (const float*)d_in[20];
    const float* thrD    = (const float*)d_in[21];

    const int SMEM_SCAN = (9216 + 16384 + 6144) * 4;   // 126976 B
    cudaFuncSetAttribute(scan_kernel, cudaFuncAttributeMaxDynamicSharedMemorySize, SMEM_SCAN);

    init_kernel<<<1600, 256>>>();
    pack1_kernel<<<(128 * 72 * 128 + 255) / 256, 256>>>(w_ih1, w_hh1, b_ih1, b_hh1);
    pack2_kernel<<<(128 * 128 * 128 + 255) / 256, 256>>>(w_ih2, w_hh2, b_ih2, b_hh2);
    conv_kernel<<<T_STEPS, 128>>>(x, conv_w);
    stats_kernel<<<OC, 256>>>(bn_g, bn_b);
    norm_kernel<<<(OC * T_STEPS * BATCH + 255) / 256, 256>>>();
    scan_kernel<<<128, 128, SMEM_SCAN>>>(thrL, thr1, thr2);
    heads_kernel<<<128, 128>>>(wg, bg, wd1, bd1, wd2, bd2, thrD, (float*)d_out);
}

// round 5
// speedup vs baseline: 2.2924x; 1.4326x over previous
#include <cuda_runtime.h>
#include <math.h>

#define T_STEPS 400
#define BATCH   128
#define HID     512
#define OC      64

typedef unsigned long long ull;

// ---------------- device scratch ----------------
__device__ float g_ybuf[OC * T_STEPS * BATCH];   // [oc][t][b]
__device__ float g_seq [T_STEPS * OC * BATCH];   // [t][c][b]
__device__ float g_scale[OC];
__device__ float g_shift[OC];
__device__ float g_memL[OC * BATCH];
__device__ float g_S1[576 * BATCH];              // rows 0-63 spikes, 64-575 mem1
__device__ float g_S2[1024 * BATCH];             // rows 0-511 spk1, 512-1023 mem2
__device__ float g_syn1[HID * BATCH];
__device__ float g_syn2[HID * BATCH];
__device__ float g_acc2[HID * BATCH];
__device__ float g_part[8 * 2048 * BATCH];       // split-K partials
__device__ unsigned g_bar_count;
__device__ volatile unsigned g_bar_phase;

// ---------------- helpers ----------------
__device__ __forceinline__ float sigf(float x) { return 1.f / (1.f + expf(-x)); }
__device__ __forceinline__ ull packf2(float w) {
    ull r; unsigned u = __float_as_uint(w);
    asm("mov.b64 %0, {%1, %1};" : "=l"(r) : "r"(u));
    return r;
}
__device__ __forceinline__ void fma2(ull& acc, ull a, ull b) {
    asm("fma.rn.f32x2 %0, %1, %2, %0;" : "+l"(acc) : "l"(a), "l"(b));
}
__device__ __forceinline__ void cpa16cg(void* dst_smem, const void* src) {
    unsigned d = (unsigned)__cvta_generic_to_shared(dst_smem);
    asm volatile("cp.async.cg.shared.global [%0], [%1], 16;" :: "r"(d), "l"(src));
}
#define CP_COMMIT() asm volatile("cp.async.commit_group;" ::: "memory")
#define CP_WAIT1()  asm volatile("cp.async.wait_group 1;"  ::: "memory")
#define CP_WAIT0()  asm volatile("cp.async.wait_group 0;"  ::: "memory")

__device__ __forceinline__ void grid_barrier() {
    __syncthreads();
    if (threadIdx.x == 0) {
        unsigned ph = g_bar_phase;
        __threadfence();
        if (atomicAdd(&g_bar_count, 1) == gridDim.x - 1) {
            g_bar_count = 0;
            __threadfence();
            g_bar_phase = ph + 1;
        } else {
            while (g_bar_phase == ph) __nanosleep(64);
        }
    }
    __syncthreads();
}

// ---------------- conv1d (pad=2, k=5): block=t, threads=b ----------------
__global__ void conv_kernel(const float* __restrict__ x, const float* __restrict__ w) {
    __shared__ float s_w[OC * 70];
    int t = blockIdx.x, b = threadIdx.x;
    for (int i = b; i < OC * 70; i += 128) s_w[i] = w[i];
    float xr[5][14];
#pragma unroll
    for (int k = 0; k < 5; k++) {
        int tt = t + k - 2;
        bool ok = (tt >= 0 && tt < T_STEPS);
#pragma unroll
        for (int c = 0; c < 14; c++)
            xr[k][c] = ok ? x[(tt * BATCH + b) * 14 + c] : 0.f;
    }
    __syncthreads();
    for (int oc = 0; oc < OC; oc++) {
        float acc = 0.f;
        const float* wr = s_w + oc * 70;
#pragma unroll
        for (int c = 0; c < 14; c++)
#pragma unroll
            for (int k = 0; k < 5; k++)
                acc = fmaf(xr[k][c], wr[c * 5 + k], acc);
        g_ybuf[oc * (T_STEPS * BATCH) + t * BATCH + b] = acc;
    }
}

__global__ void stats_kernel(const float* __restrict__ bn_g, const float* __restrict__ bn_b) {
    int c = blockIdx.x;
    const float* base = g_ybuf + c * (T_STEPS * BATCH);
    double s = 0.0, sq = 0.0;
    for (int i = threadIdx.x; i < T_STEPS * BATCH; i += 256) {
        float v = base[i];
        s += v; sq += (double)v * (double)v;
    }
    __shared__ double rs[256], rq[256];
    rs[threadIdx.x] = s; rq[threadIdx.x] = sq;
    __syncthreads();
    for (int st = 128; st > 0; st >>= 1) {
        if (threadIdx.x < st) { rs[threadIdx.x] += rs[threadIdx.x + st]; rq[threadIdx.x] += rq[threadIdx.x + st]; }
        __syncthreads();
    }
    if (threadIdx.x == 0) {
        double n = (double)(T_STEPS * BATCH);
        double mu = rs[0] / n;
        double var = rq[0] / n - mu * mu;
        float sc = bn_g[c] * (float)(1.0 / sqrt(var + 1e-5));
        g_scale[c] = sc;
        g_shift[c] = bn_b[c] - (float)mu * sc;
    }
}

__global__ void norm_kernel() {
    int i = blockIdx.x * 256 + threadIdx.x;
    if (i >= OC * T_STEPS * BATCH) return;
    int oc = i / (T_STEPS * BATCH);
    int rem = i % (T_STEPS * BATCH);
    int t = rem / BATCH, b = rem % BATCH;
    g_seq[t * (OC * BATCH) + oc * BATCH + b] = g_ybuf[i] * g_scale[oc] + g_shift[oc];
}

// ---------------- persistent scan kernel ----------------
// grid 128 = 16 gate-tiles x 8 k-splits; 256 threads; thread tile 8 gates x 8 batch
// smem: w1 [72][128] + w2 [128][128] + state dbuf [2][24*128]

template <int KS, int CH>
__device__ __forceinline__ void gemm_phase(const float* __restrict__ gstate,
                                           const float* __restrict__ wsm,
                                           float* __restrict__ spart,
                                           float* __restrict__ sbuf,
                                           int gg, int bgr)
{
    const int NCHK = KS / CH;
    const int tid = threadIdx.x;

    // prologue: fetch chunks 0 and 1
#pragma unroll
    for (int j = 0; j < CH / 8; j++) {
        int u = tid + j * 256;
        cpa16cg(sbuf + u * 4, gstate + u * 4);
    }
    CP_COMMIT();
    if (NCHK > 1) {
#pragma unroll
        for (int j = 0; j < CH / 8; j++) {
            int u = tid + j * 256;
            cpa16cg(sbuf + CH * 128 + u * 4, gstate + CH * 128 + u * 4);
        }
    }
    CP_COMMIT();

    ull acc[8][4];
#pragma unroll
    for (int j = 0; j < 8; j++)
#pragma unroll
        for (int q = 0; q < 4; q++) acc[j][q] = 0ull;

    for (int c = 0; c < NCHK; c++) {
        CP_WAIT1();
        __syncthreads();
        const float* sb = sbuf + (c & 1) * (CH * 128) + bgr * 8;
        const float* wb = wsm + c * (CH * 128) + gg * 8;
#pragma unroll 4
        for (int kk = 0; kk < CH; kk++) {
            ulonglong2 s01 = *(const ulonglong2*)(sb + kk * 128);
            ulonglong2 s23 = *(const ulonglong2*)(sb + kk * 128 + 4);
            float4 wA = *(const float4*)(wb + kk * 128);
            float4 wB = *(const float4*)(wb + kk * 128 + 4);
            float wv[8] = {wA.x, wA.y, wA.z, wA.w, wB.x, wB.y, wB.z, wB.w};
#pragma unroll
            for (int j = 0; j < 8; j++) {
                ull wp = packf2(wv[j]);
                fma2(acc[j][0], s01.x, wp);
                fma2(acc[j][1], s01.y, wp);
                fma2(acc[j][2], s23.x, wp);
                fma2(acc[j][3], s23.y, wp);
            }
        }
        __syncthreads();
        if (c + 2 < NCHK) {
            const float* src = gstate + (c + 2) * (CH * 128);
            float* dst = sbuf + (c & 1) * (CH * 128);
#pragma unroll
            for (int j = 0; j < CH / 8; j++) {
                int u = tid + j * 256;
                cpa16cg(dst + u * 4, src + u * 4);
            }
        }
        CP_COMMIT();
    }

    // write partials: rows gg*8+j, cols bgr*8..+8
#pragma unroll
    for (int j = 0; j < 8; j++) {
        float* dst = spart + (gg * 8 + j) * 128 + bgr * 8;
        ulonglong2 v0, v1;
        v0.x = acc[j][0]; v0.y = acc[j][1];
        v1.x = acc[j][2]; v1.y = acc[j][3];
        *(ulonglong2*)dst = v0;
        *(ulonglong2*)(dst + 4) = v1;
    }
}

__device__ __forceinline__ void epi_slstm(int layer, float thr,
                                          const float* __restrict__ bi,
                                          const float* __restrict__ bh) {
    float* syn  = (layer == 1) ? g_syn1 : g_syn2;
    float* memr = (layer == 1) ? (g_S1 + 64 * 128) : (g_S2 + 512 * 128);
    int tg = blockIdx.x * 256 + threadIdx.x;
#pragma unroll
    for (int e2 = 0; e2 < 2; e2++) {
        int e = tg + e2 * 32768;
        int h = e >> 7, b = e & 127;
        float sums[4];
#pragma unroll
        for (int gt = 0; gt < 4; gt++) {
            int r = gt * 512 + h;
            float s = 0.f;
#pragma unroll
            for (int sp = 0; sp < 8; sp++)
                s += __ldcg(&g_part[sp * 262144 + (r >> 7) * 16384 + (r & 127) * 128 + b]);
            sums[gt] = s + __ldg(bi + r) + __ldg(bh + r);
        }
        float sv = syn[e];
        float mo = __ldcg(&memr[e]);
        float reset = (mo > thr) ? thr : 0.f;
        float sn = sigf(sums[1]) * sv + sigf(sums[0]) * tanhf(sums[2]);
        float mn = sigf(sums[3]) * tanhf(sn) - reset;
        syn[e] = sn;
        memr[e] = mn;
        if (layer == 1) g_S2[e] = (mn > thr) ? 1.f : 0.f;
        else g_acc2[e] += mn;
    }
}

__device__ __forceinline__ void lif_phase(int t, float thrL) {
    int tg = blockIdx.x * 256 + threadIdx.x;
    if (tg < 8192) {
        float mo = g_memL[tg];
        float xt = g_seq[t * 8192 + tg];
        float reset = (mo > thrL) ? thrL : 0.f;
        float mn = 0.9f * mo + xt - reset;
        g_memL[tg] = mn;
        g_S1[tg] = (mn > thrL) ? 1.f : 0.f;
    }
}

__global__ void __launch_bounds__(256, 1) scan_kernel(
    const float* __restrict__ w_ih1, const float* __restrict__ w_hh1,
    const float* __restrict__ b_ih1, const float* __restrict__ b_hh1,
    const float* __restrict__ w_ih2, const float* __restrict__ w_hh2,
    const float* __restrict__ b_ih2, const float* __restrict__ b_hh2,
    const float* __restrict__ thrL_p, const float* __restrict__ thr1_p,
    const float* __restrict__ thr2_p)
{
    extern __shared__ float smem[];
    float* w1sm = smem;                 // 72*128  = 9216
    float* w2sm = smem + 9216;          // 128*128 = 16384
    float* sbuf = smem + 9216 + 16384;  // 2*24*128 = 6144

    const int tid = threadIdx.x;
    const int cta = blockIdx.x;
    const int tile = cta >> 3, split = cta & 7;
    const int gg = tid >> 4, bgr = tid & 15;
    const float thrL = __ldg(thrL_p), thr1 = __ldg(thr1_p), thr2 = __ldg(thr2_p);
    const int gid = cta * 256 + tid;

    // ---- prologue: zero state ----
    for (int i = gid; i < 576 * 128; i += 32768) g_S1[i] = 0.f;
    for (int i = gid; i < 1024 * 128; i += 32768) g_S2[i] = 0.f;
    for (int i = gid; i < 512 * 128; i += 32768) { g_syn1[i] = 0.f; g_syn2[i] = 0.f; g_acc2[i] = 0.f; }
    if (gid < 8192) g_memL[gid] = 0.f;

    // ---- prologue: pack weights into resident smem (transposed [k][gate]) ----
    for (int i = tid; i < 72 * 128; i += 256) {
        int kl = i >> 7, gi = i & 127;
        int r = tile * 128 + gi;
        int kg = split * 72 + kl;
        w1sm[i] = (kg < 64) ? __ldg(w_ih1 + r * 64 + kg) : __ldg(w_hh1 + r * 512 + kg - 64);
    }
    for (int i = tid; i < 128 * 128; i += 256) {
        int kl = i >> 7, gi = i & 127;
        int r = tile * 128 + gi;
        int kg = split * 128 + kl;
        w2sm[i] = (kg < 512) ? __ldg(w_ih2 + r * 512 + kg) : __ldg(w_hh2 + r * 512 + kg - 512);
    }

    float* spart = g_part + split * 262144 + tile * 16384;

    lif_phase(0, thrL);
    grid_barrier();

    for (int t = 0; t < T_STEPS; t++) {
        gemm_phase<72, 24>(g_S1 + split * (72 * 128), w1sm, spart, sbuf, gg, bgr);
        grid_barrier();
        epi_slstm(1, thr1, b_ih1, b_hh1);
        grid_barrier();
        gemm_phase<128, 16>(g_S2 + split * (128 * 128), w2sm, spart, sbuf, gg, bgr);
        grid_barrier();
        epi_slstm(2, thr2, b_ih2, b_hh2);
        if (t + 1 < T_STEPS) lif_phase(t + 1, thrL);
        grid_barrier();
    }
}

// ---------------- heads ----------------
__global__ void heads_kernel(const float* __restrict__ wg, const float* __restrict__ bg,
                             const float* __restrict__ wd1, const float* __restrict__ bd1,
                             const float* __restrict__ wd2, const float* __restrict__ bd2,
                             const float* __restrict__ thr_dom_p, float* __restrict__ out)
{
    __shared__ float feat[512];
    __shared__ float sd[64];
    int b = blockIdx.x, tid = threadIdx.x;
    const float thr = *thr_dom_p;
#pragma unroll
    for (int j = 0; j < 4; j++)
        feat[tid + j * 128] = g_acc2[(tid + j * 128) * 128 + b] * (1.f / 400.f);
    __syncthreads();
    if (tid < 8) {
        float acc = bg[tid];
        for (int h = 0; h < 512; h++) acc = fmaf(feat[h], wg[tid * 512 + h], acc);
        out[b * 8 + tid] = acc;
    }
    if (tid < 64) {
        float acc = bd1[tid];
        for (int h = 0; h < 512; h++) acc = fmaf(feat[h], wd1[tid * 512 + h], acc);
        sd[tid] = (acc - thr > 0.f) ? 1.f : 0.f;
    }
    __syncthreads();
    if (tid < 10) {
        float acc = bd2[tid];
        for (int k = 0; k < 64; k++) acc = fmaf(sd[k], wd2[tid * 64 + k], acc);
        out[128 * 8 + b * 10 + tid] = acc;
    }
}

extern "C" void kernel_launch(void* const* d_in, const int* in_sizes, int n_in,
                              void* d_out, int out_size) {
    const float* x       = (const float*)d_in[0];
    const float* conv_w  = (const float*)d_in[1];
    const float* bn_g    = (const float*)d_in[2];
    const float* bn_b    = (const float*)d_in[3];
    const float* w_ih1   = (const float*)d_in[4];
    const float* w_hh1   = (const float*)d_in[5];
    const float* b_ih1   = (const float*)d_in[6];
    const float* b_hh1   = (const float*)d_in[7];
    const float* w_ih2   = (const float*)d_in[8];
    const float* w_hh2   = (const float*)d_in[9];
    const float* b_ih2   = (const float*)d_in[10];
    const float* b_hh2   = (const float*)d_in[11];
    const float* wg      = (const float*)d_in[12];
    const float* bg      = (const float*)d_in[13];
    const float* wd1     = (const float*)d_in[14];
    const float* bd1     = (const float*)d_in[15];
    const float* wd2     = (const float*)d_in[16];
    const float* bd2     = (const float*)d_in[17];
    const float* thrL    = (const float*)d_in[18];
    const float* thr1    = (const float*)d_in[19];
    const float* thr2    = (const float*)d_in[20];
    const float* thrD    = (const float*)d_in[21];

    const int SMEM_SCAN = (9216 + 16384 + 6144) * 4;   // 126976 B
    cudaFuncSetAttribute(scan_kernel, cudaFuncAttributeMaxDynamicSharedMemorySize, SMEM_SCAN);

    conv_kernel<<<T_STEPS, 128>>>(x, conv_w);
    stats_kernel<<<OC, 256>>>(bn_g, bn_b);
    norm_kernel<<<(OC * T_STEPS * BATCH + 255) / 256, 256>>>();
    scan_kernel<<<128, 256, SMEM_SCAN>>>(w_ih1, w_hh1, b_ih1, b_hh1,
                                         w_ih2, w_hh2, b_ih2, b_hh2,
                                         thrL, thr1, thr2);
    heads_kernel<<<128, 128>>>(wg, bg, wd1, bd1, wd2, bd2, thrD, (float*)d_out);
}